// round 2
// baseline (speedup 1.0000x reference)
#include <cuda_runtime.h>

// Problem constants (fixed shapes per metadata)
#define NTOT       1572864      // 3 * 32 * 128 * 128 scores
#define W_DIM      128
#define H_DIM      128
#define CH_STRIDE  524288       // 32*128*128 (per-channel stride)
#define PRE_N      2000
#define POST_N     300
#define CAND_CAP   4096
#define NMS_T      0.7f

// ---------------- scratch (device globals; no allocation allowed) ----------
__device__ unsigned g_hist1[65536];
__device__ unsigned g_hist2[65536];
__device__ unsigned g_prefix;
__device__ unsigned g_above1;
__device__ unsigned g_thresh;
__device__ unsigned g_candCount;
__device__ unsigned long long g_cand[CAND_CAP];
__device__ int g_topIdx[PRE_N];

__device__ float g_bx1[PRE_N], g_by1[PRE_N], g_bz1[PRE_N];
__device__ float g_bx2[PRE_N], g_by2[PRE_N], g_bz2[PRE_N];
__device__ float g_vol[PRE_N], g_sc[PRE_N];

__device__ unsigned long long g_supp0[32];              // initial suppression (invalid boxes)
__device__ unsigned long long g_mask[PRE_N * 32];       // NMS suppression bitmask rows
__device__ int g_keepList[POST_N];
__device__ int g_keptCount;

// monotone map float -> uint (handles negatives for robustness)
__device__ __forceinline__ unsigned mapKey(float f) {
    unsigned b = __float_as_uint(f);
    return b ^ ((b & 0x80000000u) ? 0xFFFFFFFFu : 0x80000000u);
}

// ---------------- kernels --------------------------------------------------
__global__ void k_zero() {
    int i = blockIdx.x * blockDim.x + threadIdx.x;
    int n = blockDim.x * gridDim.x;
    for (int j = i; j < 65536; j += n) { g_hist1[j] = 0u; g_hist2[j] = 0u; }
    if (i < 32) g_supp0[i] = 0ULL;
    if (i == 0) g_candCount = 0u;
}

__global__ void k_hist1(const float* __restrict__ sc) {
    int i0 = blockIdx.x * blockDim.x + threadIdx.x;
    int n  = blockDim.x * gridDim.x;
    for (int i = i0; i < NTOT; i += n) {
        unsigned b = mapKey(sc[i]);
        atomicAdd(&g_hist1[b >> 16], 1u);
    }
}

__global__ void k_scan1() {
    __shared__ unsigned part[1024];
    __shared__ unsigned suffAfter[1024];
    int t = threadIdx.x;
    int base = t * 64;
    unsigned s = 0;
    #pragma unroll 4
    for (int i = 0; i < 64; i++) s += g_hist1[base + i];
    part[t] = s;
    __syncthreads();
    if (t == 0) {
        unsigned run = 0;
        for (int j = 1023; j >= 0; j--) { suffAfter[j] = run; run += part[j]; }
    }
    __syncthreads();
    unsigned sa = suffAfter[t];
    if (sa < PRE_N && sa + part[t] >= PRE_N) {
        unsigned run = sa;
        for (int i = 63; i >= 0; i--) {
            unsigned h = g_hist1[base + i];
            run += h;
            if (run >= PRE_N) { g_prefix = (unsigned)(base + i); g_above1 = run - h; break; }
        }
    }
}

__global__ void k_hist2(const float* __restrict__ sc) {
    unsigned p = g_prefix;
    int i0 = blockIdx.x * blockDim.x + threadIdx.x;
    int n  = blockDim.x * gridDim.x;
    for (int i = i0; i < NTOT; i += n) {
        unsigned b = mapKey(sc[i]);
        if ((b >> 16) == p) atomicAdd(&g_hist2[b & 0xFFFFu], 1u);
    }
}

__global__ void k_scan2() {
    __shared__ unsigned part[1024];
    __shared__ unsigned suffAfter[1024];
    int t = threadIdx.x;
    int base = t * 64;
    unsigned need = PRE_N - g_above1;   // >0 by construction
    unsigned s = 0;
    #pragma unroll 4
    for (int i = 0; i < 64; i++) s += g_hist2[base + i];
    part[t] = s;
    __syncthreads();
    if (t == 0) {
        unsigned run = 0;
        for (int j = 1023; j >= 0; j--) { suffAfter[j] = run; run += part[j]; }
    }
    __syncthreads();
    unsigned sa = suffAfter[t];
    if (sa < need && sa + part[t] >= need) {
        unsigned run = sa;
        for (int i = 63; i >= 0; i--) {
            unsigned h = g_hist2[base + i];
            run += h;
            if (run >= need) { g_thresh = (g_prefix << 16) | (unsigned)(base + i); break; }
        }
    }
}

// Collect candidates; record the TRANSPOSED flat index (pos*3 + a), matching
// the reference's (S,H,W,A) flatten order, so tie-break sorting is exact.
__global__ void k_collect(const float* __restrict__ sc) {
    unsigned T = g_thresh;
    int i0 = blockIdx.x * blockDim.x + threadIdx.x;
    int n  = blockDim.x * gridDim.x;
    for (int i = i0; i < NTOT; i += n) {
        unsigned b = mapKey(sc[i]);
        if (b >= T) {
            int a   = i / CH_STRIDE;      // raw layout: (A,S,H,W)
            int pos = i - a * CH_STRIDE;
            unsigned tIdx = (unsigned)(pos * 3 + a);
            unsigned p = atomicAdd(&g_candCount, 1u);
            if (p < CAND_CAP)
                g_cand[p] = ((unsigned long long)(~b) << 32) | tIdx;
        }
    }
}

// single-block bitonic sort of CAND_CAP packed keys; ascending = (score desc, idx asc)
__global__ void k_sort() {
    __shared__ unsigned long long sk[CAND_CAP];
    int t = threadIdx.x, nt = blockDim.x;
    unsigned cc = g_candCount; if (cc > CAND_CAP) cc = CAND_CAP;
    for (int i = t; i < CAND_CAP; i += nt)
        sk[i] = (i < (int)cc) ? g_cand[i] : 0xFFFFFFFFFFFFFFFFULL;
    __syncthreads();
    for (int k = 2; k <= CAND_CAP; k <<= 1) {
        for (int j = k >> 1; j > 0; j >>= 1) {
            for (int i = t; i < CAND_CAP; i += nt) {
                int ixj = i ^ j;
                if (ixj > i) {
                    bool up = ((i & k) == 0);
                    unsigned long long a = sk[i], b = sk[ixj];
                    if ((a > b) == up) { sk[i] = b; sk[ixj] = a; }
                }
            }
            __syncthreads();
        }
    }
    for (int r = t; r < PRE_N; r += nt)
        g_topIdx[r] = (int)(sk[r] & 0xFFFFFFFFu);
}

__global__ void k_transform(const float* __restrict__ sc,
                            const float* __restrict__ dl,
                            const float* __restrict__ imi,
                            const float* __restrict__ anc) {
    int r = blockIdx.x * blockDim.x + threadIdx.x;
    if (r >= PRE_N) return;
    int idx = g_topIdx[r];                // transposed flat index
    int a   = idx % 3;
    int pos = idx / 3;
    int wl  = pos % W_DIM;
    int hl  = (pos / W_DIM) % H_DIM;
    int sl  = pos / (W_DIM * H_DIM);
    float shx = wl * 4.0f, shy = hl * 4.0f, shz = sl * 4.0f;
    float ax1 = anc[a*6+0] + shx, ay1 = anc[a*6+1] + shy, az1 = anc[a*6+2] + shz;
    float ax2 = anc[a*6+3] + shx, ay2 = anc[a*6+4] + shy, az2 = anc[a*6+5] + shz;

    const float* db = dl + (size_t)(6 * a) * CH_STRIDE + pos;
    float d0 = db[0];
    float d1 = db[(size_t)CH_STRIDE];
    float d2 = db[(size_t)2 * CH_STRIDE];
    float d3 = db[(size_t)3 * CH_STRIDE];
    float d4 = db[(size_t)4 * CH_STRIDE];
    float d5 = db[(size_t)5 * CH_STRIDE];

    float w_ = ax2 - ax1 + 1.0f, h_ = ay2 - ay1 + 1.0f, dd = az2 - az1 + 1.0f;
    float cx = ax1 + 0.5f * w_, cy = ay1 + 0.5f * h_, cz = az1 + 0.5f * dd;
    float pcx = d0 * w_ + cx, pcy = d1 * h_ + cy, pcz = d2 * dd + cz;
    float pw = expf(d3) * w_, ph = expf(d4) * h_, pd = expf(d5) * dd;

    float slices = imi[0], height = imi[1], width = imi[2], scale = imi[3];
    float x1 = fminf(fmaxf(pcx - 0.5f * pw, 0.0f), width  - 1.0f);
    float y1 = fminf(fmaxf(pcy - 0.5f * ph, 0.0f), height - 1.0f);
    float z1 = fminf(fmaxf(pcz - 0.5f * pd, 0.0f), slices - 1.0f);
    float x2 = fminf(fmaxf(pcx + 0.5f * pw - 1.0f, 0.0f), width  - 1.0f);
    float y2 = fminf(fmaxf(pcy + 0.5f * ph - 1.0f, 0.0f), height - 1.0f);
    float z2 = fminf(fmaxf(pcz + 0.5f * pd - 1.0f, 0.0f), slices - 1.0f);

    g_bx1[r] = x1; g_by1[r] = y1; g_bz1[r] = z1;
    g_bx2[r] = x2; g_by2[r] = y2; g_bz2[r] = z2;
    g_vol[r] = (x2 - x1 + 1.0f) * (y2 - y1 + 1.0f) * (z2 - z1 + 1.0f);
    g_sc[r]  = sc[(size_t)a * CH_STRIDE + pos];   // raw layout gather

    float ss = x2 - x1 + 1.0f;
    float xc = x1 + ss * 0.5f, yc = y1 + ss * 0.5f, zc = z1 + ss * 0.5f;
    bool valid = (ss >= 8.0f * scale) && (xc < width) && (yc < height) && (zc < slices);
    if (!valid) atomicOr(&g_supp0[r >> 6], 1ULL << (r & 63));
}

// 64x64-tile suppression bitmask; bit set iff (iou > 0.7) && (j > i)
__global__ void k_mask() {
    int by = blockIdx.y, bx = blockIdx.x;
    int t = threadIdx.x;
    if (bx < by) {                       // whole tile has j < i
        int i = by * 64 + t;
        if (i < PRE_N) g_mask[(size_t)i * 32 + bx] = 0ULL;
        return;
    }
    __shared__ float cx1[64], cy1[64], cz1[64], cx2[64], cy2[64], cz2[64], cv[64];
    int j = bx * 64 + t;
    if (j < PRE_N) {
        cx1[t] = g_bx1[j]; cy1[t] = g_by1[j]; cz1[t] = g_bz1[j];
        cx2[t] = g_bx2[j]; cy2[t] = g_by2[j]; cz2[t] = g_bz2[j];
        cv[t]  = g_vol[j];
    }
    __syncthreads();
    int i = by * 64 + t;
    if (i >= PRE_N) return;
    float x1 = g_bx1[i], y1 = g_by1[i], z1 = g_bz1[i];
    float x2 = g_bx2[i], y2 = g_by2[i], z2 = g_bz2[i];
    float v  = g_vol[i];
    unsigned long long m = 0ULL;
    int jmax = PRE_N - bx * 64; if (jmax > 64) jmax = 64;
    for (int c = 0; c < jmax; c++) {
        int jg = bx * 64 + c;
        if (jg <= i) continue;
        float iw = fmaxf(fminf(x2, cx2[c]) - fmaxf(x1, cx1[c]) + 1.0f, 0.0f);
        float ih = fmaxf(fminf(y2, cy2[c]) - fmaxf(y1, cy1[c]) + 1.0f, 0.0f);
        float id = fmaxf(fminf(z2, cz2[c]) - fmaxf(z1, cz1[c]) + 1.0f, 0.0f);
        float inter = iw * ih * id;
        float iou = inter / (v + cv[c] - inter);
        if (iou > NMS_T) m |= (1ULL << c);
    }
    g_mask[(size_t)i * 32 + bx] = m;
}

// 1-warp greedy reduce with early exit at POST_N kept
__global__ void k_reduce() {
    int lane = threadIdx.x;              // 32 threads
    unsigned long long remv = g_supp0[lane];
    int kept = 0;
    for (int i = 0; i < PRE_N; i++) {
        unsigned long long w = __shfl_sync(0xFFFFFFFFu, remv, i >> 6);
        bool k = !((w >> (i & 63)) & 1ULL);
        if (k) {
            remv |= g_mask[(size_t)i * 32 + lane];
            if (lane == 0) g_keepList[kept] = i;
            kept++;
            if (kept == POST_N) break;
        }
    }
    if (lane == 0) g_keptCount = kept;
}

__global__ void k_out(float* __restrict__ out, int out_size) {
    int s = blockIdx.x * blockDim.x + threadIdx.x;
    if (s >= POST_N) return;
    int kc = g_keptCount;
    float b0, b1, b2, b3, b4, b5, scv, kidx, vld;
    if (s < kc) {
        int i = g_keepList[s];
        b0 = g_bx1[i]; b1 = g_by1[i]; b2 = g_bz1[i];
        b3 = g_bx2[i]; b4 = g_by2[i]; b5 = g_bz2[i];
        scv = g_sc[i]; kidx = (float)g_topIdx[i]; vld = 1.0f;
    } else {
        b0 = b1 = b2 = b3 = b4 = b5 = 0.0f;
        scv = 0.0f; kidx = -1.0f; vld = 0.0f;
    }
    int base = s * 7;
    out[base + 0] = 0.0f;
    out[base + 1] = b0; out[base + 2] = b1; out[base + 3] = b2;
    out[base + 4] = b3; out[base + 5] = b4; out[base + 6] = b5;
    if (out_size >= POST_N * 7 + POST_N)     out[POST_N * 7 + s] = scv;
    if (out_size >= POST_N * 8 + POST_N)     out[POST_N * 8 + s] = kidx;
    if (out_size >= POST_N * 9 + POST_N)     out[POST_N * 9 + s] = vld;
}

// ---------------- launcher --------------------------------------------------
extern "C" void kernel_launch(void* const* d_in, const int* in_sizes, int n_in,
                              void* d_out, int out_size) {
    const float* sc  = (const float*)d_in[0];   // rpn_cls_prob  (1,3,32,128,128)
    const float* dl  = (const float*)d_in[1];   // rpn_bbox_pred (1,18,32,128,128)
    const float* imi = (const float*)d_in[2];   // im_info (1,4)
    const float* anc = (const float*)d_in[3];   // anchors (3,6)
    float* out = (float*)d_out;

    k_zero   <<<256, 256>>>();
    k_hist1  <<<1536, 256>>>(sc);
    k_scan1  <<<1, 1024>>>();
    k_hist2  <<<1536, 256>>>(sc);
    k_scan2  <<<1, 1024>>>();
    k_collect<<<1536, 256>>>(sc);
    k_sort   <<<1, 512>>>();
    k_transform<<<(PRE_N + 255) / 256, 256>>>(sc, dl, imi, anc);
    k_mask   <<<dim3(32, 32), 64>>>();
    k_reduce <<<1, 32>>>();
    k_out    <<<(POST_N + 255) / 256, 256>>>(out, out_size);
}